// round 1
// baseline (speedup 1.0000x reference)
#include <cuda_runtime.h>
#include <stdint.h>

// Problem constants (fixed shapes per reference)
#define NUM_NODES 100000
#define NUM_EDGES 400000
#define ROUNDS 18   // ceil(log2(100000)) = 17, +1 margin

// Scratch (no cudaMalloc allowed)
__device__ unsigned long long g_key[NUM_EDGES];
__device__ int                g_label[NUM_NODES];
__device__ unsigned long long g_best[NUM_NODES];

// ---------------------------------------------------------------------------
// Init: compute order keys bitwise-matching the JAX f32 pipeline, init
// union-find labels, clear best[], zero output.
//   score = sigmoid(s) + (-log(-log(u + 1e-9) + 1e-9))
//   sigmoid via 1/(1+expf(-x)) : libdevice __nv_expf + IEEE div (no fast math)
//   logf -> libdevice __nv_logf (same as XLA GPU lowering)
// Key: (monotone_u32(score) << 32) | (0xFFFFFFFF - idx)
//   => max key == highest score, ties broken by LOWEST index (stable argsort).
// ---------------------------------------------------------------------------
__global__ void k_init(const float* __restrict__ s,
                       const float* __restrict__ u,
                       float* __restrict__ out)
{
    int i = blockIdx.x * blockDim.x + threadIdx.x;
    if (i < NUM_EDGES) {
        float sp = 1.0f / (1.0f + expf(-s[i]));
        float gb = -logf(-logf(u[i] + 1e-9f) + 1e-9f);
        float sc = sp + gb;
        unsigned ub = __float_as_uint(sc);
        // order-preserving float->uint map (finite values)
        ub = (ub & 0x80000000u) ? ~ub : (ub | 0x80000000u);
        g_key[i] = ((unsigned long long)ub << 32)
                 | (unsigned long long)(0xFFFFFFFFu - (unsigned)i);
        out[i] = 0.0f;
    }
    if (i < NUM_NODES) {
        g_label[i] = i;
        g_best[i]  = 0ULL;
    }
}

// ---------------------------------------------------------------------------
// Boruvka round, phase A: per-component best incident external edge.
// Labels are flattened at this point (label[v] == root id).
// ---------------------------------------------------------------------------
__global__ void k_best(const int* __restrict__ src,
                       const int* __restrict__ dst)
{
    int e = blockIdx.x * blockDim.x + threadIdx.x;
    if (e >= NUM_EDGES) return;
    int lu = g_label[src[e]];
    int lv = g_label[dst[e]];
    if (lu != lv) {
        unsigned long long k = g_key[e];
        atomicMax(&g_best[lu], k);
        atomicMax(&g_best[lv], k);
    }
}

// ---------------------------------------------------------------------------
// Phase B: hook. Each root with a best edge hooks to the other endpoint's
// root and marks the edge accepted. Mutual 2-cycles (both roots picked the
// same edge) are broken: only the larger-id root hooks. Races with concurrent
// hooks are benign (pointer shortcuts only; guarded by other==i check).
// ---------------------------------------------------------------------------
__global__ void k_hook(const int* __restrict__ src,
                       const int* __restrict__ dst,
                       float* __restrict__ out)
{
    int i = blockIdx.x * blockDim.x + threadIdx.x;
    if (i >= NUM_NODES) return;
    unsigned long long bk = g_best[i];
    if (bk == 0ULL) return;            // no external edge (or not a root)
    int e  = (int)(0xFFFFFFFFu - (unsigned)(bk & 0xFFFFFFFFull));
    int lu = g_label[src[e]];
    int lv = g_label[dst[e]];
    int other = lu ^ lv ^ i;           // one of lu,lv is i (own entry stable)
    if (other == i) return;            // partner already hooked into us
    if (g_best[other] == bk) {
        // mutual pair: larger root hooks under smaller, marks the edge once
        if (i > other) { g_label[i] = other; out[e] = 1.0f; }
    } else {
        g_label[i] = other;
        out[e] = 1.0f;
    }
}

// ---------------------------------------------------------------------------
// Phase C: flatten labels (pointer-chase to root; hooked graph is a forest,
// concurrent writes only shortcut toward the root) and reset best[].
// ---------------------------------------------------------------------------
__global__ void k_flat()
{
    int i = blockIdx.x * blockDim.x + threadIdx.x;
    if (i >= NUM_NODES) return;
    int r = g_label[i];
    #pragma unroll 1
    while (true) {
        int p = g_label[r];
        if (p == r) break;
        r = p;
    }
    g_label[i] = r;
    g_best[i]  = 0ULL;
}

extern "C" void kernel_launch(void* const* d_in, const int* in_sizes, int n_in,
                              void* d_out, int out_size)
{
    const float* s  = (const float*)d_in[0];
    const float* u  = (const float*)d_in[1];
    const int*   ei = (const int*)d_in[2];   // [2, E] row-major
    const int*   src = ei;
    const int*   dst = ei + NUM_EDGES;
    float* out = (float*)d_out;

    const int TB = 256;
    const int gE = (NUM_EDGES + TB - 1) / TB;
    const int gN = (NUM_NODES + TB - 1) / TB;

    k_init<<<gE, TB>>>(s, u, out);
    for (int r = 0; r < ROUNDS; ++r) {
        k_best<<<gE, TB>>>(src, dst);
        k_hook<<<gN, TB>>>(src, dst, out);
        k_flat<<<gN, TB>>>();
    }
}

// round 2
// speedup vs baseline: 1.1363x; 1.1363x over previous
#include <cuda_runtime.h>
#include <stdint.h>

// Problem constants (fixed shapes per reference)
#define NUM_NODES 100000
#define NUM_EDGES 400000
#define MAXR      20          // Boruvka needs <= ceil(log2(N)); early-exit typically ~7
#define BLOCKS    148         // <= SM count on B300/GB300 -> 1 block/SM co-resident
#define TPB       1024
#define NT        (BLOCKS * TPB)

// Scratch (no cudaMalloc allowed)
__device__ unsigned long long g_key[NUM_EDGES];
__device__ int                g_label[NUM_NODES];
__device__ unsigned long long g_best[NUM_NODES];
__device__ int                g_changed[MAXR];
__device__ unsigned           g_count = 0;   // barrier arrival counter
__device__ unsigned           g_gen   = 0;   // barrier generation (wrap-safe, persists across replays)

// ---------------------------------------------------------------------------
// Acquire/release helpers for the software grid barrier. The release on g_gen
// by the last arriver + acquire by spinners makes all pre-barrier writes
// (including L2 atomics) visible to post-barrier plain loads.
// ---------------------------------------------------------------------------
__device__ __forceinline__ unsigned ld_acq(const unsigned* p) {
    unsigned v;
    asm volatile("ld.acquire.gpu.u32 %0, [%1];" : "=r"(v) : "l"(p) : "memory");
    return v;
}
__device__ __forceinline__ void st_rel(unsigned* p, unsigned v) {
    asm volatile("st.release.gpu.u32 [%0], %1;" :: "l"(p), "r"(v) : "memory");
}

__device__ __forceinline__ void gbar() {
    __syncthreads();
    if (threadIdx.x == 0) {
        unsigned my = ld_acq(&g_gen);      // gen can't advance until I arrive
        __threadfence();                   // release my block's writes
        unsigned a = atomicAdd(&g_count, 1u);
        if (a == BLOCKS - 1) {
            g_count = 0;                   // ordered before the release below
            __threadfence();
            st_rel(&g_gen, my + 1u);
        } else {
            while (ld_acq(&g_gen) == my) __nanosleep(32);
        }
    }
    __syncthreads();
}

// ---------------------------------------------------------------------------
// Persistent Boruvka (maximum spanning forest).
// Keys bitwise-match the JAX f32 pipeline (validated rel_err==0.0):
//   score = 1/(1+expf(-s)) + (-logf(-logf(u+1e-9)+1e-9))
// Key: (monotone_u32(score) << 32) | (0xFFFFFFFF - idx)
//   -> max key = highest score, ties broken by LOWEST index (stable argsort).
// ---------------------------------------------------------------------------
__global__ void __launch_bounds__(TPB, 1)
boruvka_kernel(const float* __restrict__ s,
               const float* __restrict__ u,
               const int*   __restrict__ src,
               const int*   __restrict__ dst,
               float*       __restrict__ out)
{
    const int tid = blockIdx.x * TPB + threadIdx.x;

    // ---- init: keys, labels, best, changed, output ----
    for (int i = tid; i < NUM_EDGES; i += NT) {
        float sp = 1.0f / (1.0f + expf(-s[i]));
        float gb = -logf(-logf(u[i] + 1e-9f) + 1e-9f);
        unsigned ub = __float_as_uint(sp + gb);
        ub = (ub & 0x80000000u) ? ~ub : (ub | 0x80000000u);  // order-preserving map
        g_key[i] = ((unsigned long long)ub << 32)
                 | (unsigned long long)(0xFFFFFFFFu - (unsigned)i);
        out[i] = 0.0f;
    }
    for (int i = tid; i < NUM_NODES; i += NT) {
        g_label[i] = i;
        g_best[i]  = 0ULL;
    }
    if (tid < MAXR) g_changed[tid] = 0;
    gbar();

    for (int r = 0; r < MAXR; ++r) {
        // ---- phase A: per-component best external edge (labels are flat) ----
        for (int e = tid; e < NUM_EDGES; e += NT) {
            int lu = g_label[src[e]];
            int lv = g_label[dst[e]];
            if (lu != lv) {
                unsigned long long k = g_key[e];
                atomicMax(&g_best[lu], k);
                atomicMax(&g_best[lv], k);
            }
        }
        gbar();

        // ---- phase B: hook roots, mark accepted edges ----
        int any = 0;
        for (int i = tid; i < NUM_NODES; i += NT) {
            unsigned long long bk = g_best[i];
            if (bk == 0ULL) continue;      // no external edge
            int e  = (int)(0xFFFFFFFFu - (unsigned)(bk & 0xFFFFFFFFull));
            int lu = g_label[src[e]];
            int lv = g_label[dst[e]];
            int other = lu ^ lv ^ i;       // one endpoint's label is i
            if (other == i) continue;
            if (g_best[other] == bk) {
                // mutual pair: only the larger-id root hooks (breaks the 2-cycle);
                // edge marked exactly once. Longer cycles impossible: keys unique.
                if (i > other) { g_label[i] = other; out[e] = 1.0f; any = 1; }
            } else {
                g_label[i] = other; out[e] = 1.0f; any = 1;
            }
        }
        if (any) g_changed[r] = 1;         // per-round flag: no reset race
        gbar();

        if (!g_changed[r]) break;          // uniform across all threads

        // ---- phase C: flatten labels + reset best ----
        for (int i = tid; i < NUM_NODES; i += NT) {
            int v = g_label[i];
            int p = g_label[v];
            #pragma unroll 1
            while (p != v) { v = p; p = g_label[v]; }
            g_label[i] = v;
            g_best[i]  = 0ULL;
        }
        gbar();
    }
}

extern "C" void kernel_launch(void* const* d_in, const int* in_sizes, int n_in,
                              void* d_out, int out_size)
{
    const float* s   = (const float*)d_in[0];
    const float* u   = (const float*)d_in[1];
    const int*   ei  = (const int*)d_in[2];   // [2, E] row-major
    const int*   src = ei;
    const int*   dst = ei + NUM_EDGES;
    float*       out = (float*)d_out;

    boruvka_kernel<<<BLOCKS, TPB>>>(s, u, src, dst, out);
}